// round 2
// baseline (speedup 1.0000x reference)
#include <cuda_runtime.h>
#include <cstdint>

// Problem constants (fixed by the reference)
#define N_NODES 65536
#define N_EDGES 1048576
#define FEAT    64

// Scratch: support = X @ W  (16 MB, device global — no allocations allowed)
__device__ float g_support[(size_t)N_NODES * FEAT];

// ---------------------------------------------------------------------------
// Kernel 1: GEMM  support[N,64] = X[N,64] @ W[64,64]
// Block = 256 threads handles 64 rows. Each thread: 4 rows x 4 cols register tile.
// ---------------------------------------------------------------------------
__global__ __launch_bounds__(256) void gemm64(const float* __restrict__ X,
                                              const float* __restrict__ W) {
    __shared__ float4 Ws[64][16];   // W[k][c4]
    __shared__ float4 Xs[64][16];   // X[r][k4]

    const int tid  = threadIdx.x;
    const int base = blockIdx.x * 64;

    const float4* X4 = (const float4*)(X + (size_t)base * FEAT);
    const float4* W4 = (const float4*)W;
    float4* XsF = (float4*)Xs;
    float4* WsF = (float4*)Ws;
#pragma unroll
    for (int i = 0; i < 4; i++) {
        int idx = tid + i * 256;
        XsF[idx] = X4[idx];
        WsF[idx] = W4[idx];
    }
    __syncthreads();

    const int rt = tid >> 4;   // 0..15  (row within group)
    const int ct = tid & 15;   // 0..15  (col quad)

    float4 acc[4];
#pragma unroll
    for (int i = 0; i < 4; i++) acc[i] = make_float4(0.f, 0.f, 0.f, 0.f);

#pragma unroll
    for (int kk = 0; kk < 16; kk++) {
        const float4 w0 = Ws[kk * 4 + 0][ct];
        const float4 w1 = Ws[kk * 4 + 1][ct];
        const float4 w2 = Ws[kk * 4 + 2][ct];
        const float4 w3 = Ws[kk * 4 + 3][ct];
#pragma unroll
        for (int i = 0; i < 4; i++) {
            const float4 x = Xs[rt + 16 * i][kk];
            acc[i].x += x.x * w0.x + x.y * w1.x + x.z * w2.x + x.w * w3.x;
            acc[i].y += x.x * w0.y + x.y * w1.y + x.z * w2.y + x.w * w3.y;
            acc[i].z += x.x * w0.z + x.y * w1.z + x.z * w2.z + x.w * w3.z;
            acc[i].w += x.x * w0.w + x.y * w1.w + x.z * w2.w + x.w * w3.w;
        }
    }

    float4* S4 = (float4*)(g_support + (size_t)base * FEAT);
#pragma unroll
    for (int i = 0; i < 4; i++)
        S4[(rt + 16 * i) * 16 + ct] = acc[i];
}

// ---------------------------------------------------------------------------
// Kernel 2: zero the output accumulator (d_out is poisoned 0xAA by harness)
// ---------------------------------------------------------------------------
__global__ __launch_bounds__(256) void zero_out(float4* __restrict__ out) {
    const unsigned i = blockIdx.x * 256u + threadIdx.x;   // over N*64/4 float4s
    out[i] = make_float4(0.f, 0.f, 0.f, 0.f);
}

// ---------------------------------------------------------------------------
// Kernel 3: COO scatter  out[row] += val * support[col]
// 16 threads per edge, each handles one float4 (4 features) via red.global.v4
// ---------------------------------------------------------------------------
__global__ __launch_bounds__(256) void scatter_edges(const int*   __restrict__ erow,
                                                     const int*   __restrict__ ecol,
                                                     const float* __restrict__ eval,
                                                     float*       __restrict__ out) {
    const unsigned gid = blockIdx.x * 256u + threadIdx.x;
    const unsigned e = gid >> 4;          // edge index
    const unsigned q = (gid & 15u) << 2;  // feature quad offset (0,4,...,60)

    const int   r = erow[e];
    const int   c = ecol[e];
    const float v = eval[e];

    const float4 m = *(const float4*)(g_support + (size_t)c * FEAT + q);
    float* p = out + (size_t)r * FEAT + q;
    asm volatile("red.global.add.v4.f32 [%0], {%1, %2, %3, %4};"
                 :: "l"(p), "f"(m.x * v), "f"(m.y * v), "f"(m.z * v), "f"(m.w * v)
                 : "memory");
}

// ---------------------------------------------------------------------------
// Kernel 4: out = relu(out + bias), vectorized float4, in place
// ---------------------------------------------------------------------------
__global__ __launch_bounds__(256) void finalize(float4* __restrict__ out,
                                                const float4* __restrict__ bias4) {
    const unsigned i = blockIdx.x * 256u + threadIdx.x;  // over N*64/4 float4s
    const float4 b = bias4[i & 15u];                     // 16 float4 per row
    float4 o = out[i];
    o.x = fmaxf(o.x + b.x, 0.f);
    o.y = fmaxf(o.y + b.y, 0.f);
    o.z = fmaxf(o.z + b.z, 0.f);
    o.w = fmaxf(o.w + b.w, 0.f);
    out[i] = o;
}

// ---------------------------------------------------------------------------
// Entry point. Input order (metadata): input, edge_rows, edge_cols, edge_vals,
// weight, bias. Output: float32 [N_NODES, 64].
// ---------------------------------------------------------------------------
extern "C" void kernel_launch(void* const* d_in, const int* in_sizes, int n_in,
                              void* d_out, int out_size) {
    const float* X    = (const float*)d_in[0];
    const int*   erow = (const int*)  d_in[1];
    const int*   ecol = (const int*)  d_in[2];
    const float* eval = (const float*)d_in[3];
    const float* W    = (const float*)d_in[4];
    const float* bias = (const float*)d_in[5];
    float* out = (float*)d_out;

    // 1) support = X @ W
    gemm64<<<N_NODES / 64, 256>>>(X, W);

    // 2) out = 0
    const int nvec4 = N_NODES * FEAT / 4;            // 1M float4
    zero_out<<<nvec4 / 256, 256>>>((float4*)out);

    // 3) scatter-add edges (16 threads per edge)
    scatter_edges<<<(N_EDGES * 16) / 256, 256>>>(erow, ecol, eval, out);

    // 4) bias + relu
    finalize<<<nvec4 / 256, 256>>>((float4*)out, (const float4*)bias);
}

// round 3
// speedup vs baseline: 1.1327x; 1.1327x over previous
#include <cuda_runtime.h>
#include <cstdint>

#define N_NODES 65536
#define N_EDGES 1048576
#define FEAT    64

// ------------------------- device scratch (no allocs) -----------------------
__device__ float g_support[(size_t)N_NODES * FEAT];  // 16 MB: X @ W
__device__ int   g_cnt[N_NODES];                     // per-row edge counts
__device__ int   g_rs[N_NODES + 1];                  // CSR row_start
__device__ int   g_cur[N_NODES];                     // scatter cursors
__device__ int   g_bsum[256];                        // block sums for scan
__device__ int   g_boff[256];                        // block offsets for scan
__device__ int2  g_epair[N_EDGES];                   // CSR (col, val-bits)

// ---------------------------------------------------------------------------
// Kernel 1: GEMM  support[N,64] = X[N,64] @ W[64,64]
// 256 threads / 64 rows per block; 4x4 register tile per thread.
// ---------------------------------------------------------------------------
__global__ __launch_bounds__(256) void gemm64(const float* __restrict__ X,
                                              const float* __restrict__ W) {
    __shared__ float4 Ws[64][16];
    __shared__ float4 Xs[64][16];

    const int tid  = threadIdx.x;
    const int base = blockIdx.x * 64;

    const float4* X4 = (const float4*)(X + (size_t)base * FEAT);
    const float4* W4 = (const float4*)W;
    float4* XsF = (float4*)Xs;
    float4* WsF = (float4*)Ws;
#pragma unroll
    for (int i = 0; i < 4; i++) {
        int idx = tid + i * 256;
        XsF[idx] = X4[idx];
        WsF[idx] = W4[idx];
    }
    __syncthreads();

    const int rt = tid >> 4;
    const int ct = tid & 15;

    float4 acc[4];
#pragma unroll
    for (int i = 0; i < 4; i++) acc[i] = make_float4(0.f, 0.f, 0.f, 0.f);

#pragma unroll
    for (int kk = 0; kk < 16; kk++) {
        const float4 w0 = Ws[kk * 4 + 0][ct];
        const float4 w1 = Ws[kk * 4 + 1][ct];
        const float4 w2 = Ws[kk * 4 + 2][ct];
        const float4 w3 = Ws[kk * 4 + 3][ct];
#pragma unroll
        for (int i = 0; i < 4; i++) {
            const float4 x = Xs[rt + 16 * i][kk];
            acc[i].x += x.x * w0.x + x.y * w1.x + x.z * w2.x + x.w * w3.x;
            acc[i].y += x.x * w0.y + x.y * w1.y + x.z * w2.y + x.w * w3.y;
            acc[i].z += x.x * w0.z + x.y * w1.z + x.z * w2.z + x.w * w3.z;
            acc[i].w += x.x * w0.w + x.y * w1.w + x.z * w2.w + x.w * w3.w;
        }
    }

    float4* S4 = (float4*)(g_support + (size_t)base * FEAT);
#pragma unroll
    for (int i = 0; i < 4; i++)
        S4[(rt + 16 * i) * 16 + ct] = acc[i];
}

// ---------------------------------------------------------------------------
// CSR build step 1: zero counters
// ---------------------------------------------------------------------------
__global__ __launch_bounds__(256) void zero_cnt() {
    g_cnt[blockIdx.x * 256 + threadIdx.x] = 0;
}

// CSR build step 2: histogram of destination rows
__global__ __launch_bounds__(256) void hist(const int* __restrict__ erow) {
    const unsigned e = blockIdx.x * 256u + threadIdx.x;
    atomicAdd(&g_cnt[erow[e]], 1);
}

// ---------------------------------------------------------------------------
// CSR build step 3: three-phase exclusive scan of g_cnt -> g_rs
// ---------------------------------------------------------------------------
__device__ __forceinline__ int block_incl_scan(int v, int* wsum) {
    const int lane = threadIdx.x & 31, wid = threadIdx.x >> 5;
    int x = v;
#pragma unroll
    for (int d = 1; d < 32; d <<= 1) {
        int y = __shfl_up_sync(0xFFFFFFFFu, x, d);
        if (lane >= d) x += y;
    }
    if (lane == 31) wsum[wid] = x;
    __syncthreads();
    if (wid == 0) {
        int w = (lane < 8) ? wsum[lane] : 0;
#pragma unroll
        for (int d = 1; d < 8; d <<= 1) {
            int y = __shfl_up_sync(0xFFFFFFFFu, w, d);
            if (lane >= d) w += y;
        }
        if (lane < 8) wsum[lane] = w;
    }
    __syncthreads();
    return x + (wid > 0 ? wsum[wid - 1] : 0);
}

__global__ __launch_bounds__(256) void scanA() {
    __shared__ int wsum[8];
    const int i = blockIdx.x * 256 + threadIdx.x;
    const int v = g_cnt[i];
    const int incl = block_incl_scan(v, wsum);
    g_rs[i] = incl - v;                         // exclusive, pre-offset
    if (threadIdx.x == 255) g_bsum[blockIdx.x] = incl;
}

__global__ __launch_bounds__(256) void scanB() {
    __shared__ int wsum[8];
    const int t = threadIdx.x;
    const int v = g_bsum[t];
    const int incl = block_incl_scan(v, wsum);
    g_boff[t] = incl - v;
}

__global__ __launch_bounds__(256) void scanC() {
    const int i = blockIdx.x * 256 + threadIdx.x;
    const int rs = g_rs[i] + g_boff[blockIdx.x];
    g_rs[i]  = rs;
    g_cur[i] = rs;
    if (i == 0) g_rs[N_NODES] = N_EDGES;
}

// ---------------------------------------------------------------------------
// CSR build step 4: reorder edges into (col, val) pairs grouped by row
// ---------------------------------------------------------------------------
__global__ __launch_bounds__(256) void reorder(const int*   __restrict__ erow,
                                               const int*   __restrict__ ecol,
                                               const float* __restrict__ eval) {
    const unsigned e = blockIdx.x * 256u + threadIdx.x;
    const int r = erow[e];
    const int pos = atomicAdd(&g_cur[r], 1);
    g_epair[pos] = make_int2(ecol[e], __float_as_int(eval[e]));
}

// ---------------------------------------------------------------------------
// Kernel: atomic-free SpMM + bias + ReLU (fused epilogue)
// 16 threads per row (one float4 of features each); 16 rows per block.
// ---------------------------------------------------------------------------
__global__ __launch_bounds__(256) void spmm_fused(float* __restrict__ out,
                                                  const float4* __restrict__ bias4) {
    const int r  = blockIdx.x * 16 + (threadIdx.x >> 4);
    const int qi = threadIdx.x & 15;       // which float4 of the row
    const int q  = qi << 2;

    const int s = g_rs[r];
    const int e = g_rs[r + 1];

    float4 acc = make_float4(0.f, 0.f, 0.f, 0.f);
    for (int i = s; i < e; i++) {
        const int2 p = g_epair[i];
        const float v = __int_as_float(p.y);
        const float4 m = *(const float4*)(g_support + (size_t)p.x * FEAT + q);
        acc.x += v * m.x;
        acc.y += v * m.y;
        acc.z += v * m.z;
        acc.w += v * m.w;
    }

    const float4 b = bias4[qi];
    acc.x = fmaxf(acc.x + b.x, 0.f);
    acc.y = fmaxf(acc.y + b.y, 0.f);
    acc.z = fmaxf(acc.z + b.z, 0.f);
    acc.w = fmaxf(acc.w + b.w, 0.f);
    ((float4*)out)[(size_t)r * 16 + qi] = acc;
}

// ---------------------------------------------------------------------------
extern "C" void kernel_launch(void* const* d_in, const int* in_sizes, int n_in,
                              void* d_out, int out_size) {
    const float* X    = (const float*)d_in[0];
    const int*   erow = (const int*)  d_in[1];
    const int*   ecol = (const int*)  d_in[2];
    const float* eval = (const float*)d_in[3];
    const float* W    = (const float*)d_in[4];
    const float* bias = (const float*)d_in[5];
    float* out = (float*)d_out;

    // CSR build (independent of GEMM result)
    zero_cnt<<<N_NODES / 256, 256>>>();
    hist<<<N_EDGES / 256, 256>>>(erow);

    // GEMM (overlappable work placed between scan dependencies is still serial
    // on one stream; order chosen to keep dependencies trivially satisfied)
    gemm64<<<N_NODES / 64, 256>>>(X, W);

    scanA<<<256, 256>>>();
    scanB<<<1, 256>>>();
    scanC<<<256, 256>>>();
    reorder<<<N_EDGES / 256, 256>>>(erow, ecol, eval);

    // Fused SpMM + bias + ReLU (atomic-free)
    spmm_fused<<<N_NODES / 16, 256>>>(out, (const float4*)bias);
}

// round 4
// speedup vs baseline: 1.2075x; 1.0660x over previous
#include <cuda_runtime.h>
#include <cuda_fp16.h>
#include <cstdint>

#define N_NODES 65536
#define N_EDGES 1048576
#define FEAT    64

// ------------------------- device scratch (no allocs) -----------------------
__device__ __align__(16) __half g_support_h[(size_t)N_NODES * FEAT]; // 8 MB fp16 support
__device__ __align__(16) int   g_cnt[N_NODES];
__device__ __align__(16) int   g_rs[N_NODES + 4];     // CSR row_start (+pad)
__device__ __align__(16) int   g_cur[N_NODES];
__device__ __align__(16) int   g_bsum[64];
__device__ __align__(16) int   g_boff[64];
__device__ __align__(16) int2  g_epair[N_EDGES];      // CSR (col, val-bits)

// ---- packed f32x2 helpers (ptxas won't auto-fuse; PTX only) ----------------
__device__ __forceinline__ unsigned long long pk2(float x, float y) {
    unsigned long long r;
    asm("mov.b64 %0, {%1, %2};" : "=l"(r) : "f"(x), "f"(y));
    return r;
}
__device__ __forceinline__ void fma2(unsigned long long& d,
                                     unsigned long long a, unsigned long long b) {
    asm("fma.rn.f32x2 %0, %1, %2, %0;" : "+l"(d) : "l"(a), "l"(b));
}
__device__ __forceinline__ float2 up2(unsigned long long v) {
    float2 f;
    asm("mov.b64 {%0, %1}, %2;" : "=f"(f.x), "=f"(f.y) : "l"(v));
    return f;
}

// ---------------------------------------------------------------------------
// Kernel 1: GEMM  support[N,64] = X[N,64] @ W[64,64], fp16 output
// 256 threads / 64 rows per block; 4 rows x 4 cols per thread, f32x2 FMA.
// ---------------------------------------------------------------------------
__global__ __launch_bounds__(256) void gemm64(const float* __restrict__ X,
                                              const float* __restrict__ W) {
    __shared__ float4 Ws[64][16];   // W[k][colquad]
    __shared__ float4 Xs[64][16];   // X[r][kquad]

    const int tid  = threadIdx.x;
    const int base = blockIdx.x * 64;

    const float4* X4 = (const float4*)(X + (size_t)base * FEAT);
    const float4* W4 = (const float4*)W;
    float4* XsF = (float4*)Xs;
    float4* WsF = (float4*)Ws;
#pragma unroll
    for (int i = 0; i < 4; i++) {
        int idx = tid + i * 256;
        XsF[idx] = X4[idx];
        WsF[idx] = W4[idx];
    }
    __syncthreads();

    const int rt = tid >> 4;   // row in group
    const int ct = tid & 15;   // col quad

    unsigned long long acc[4][2];
#pragma unroll
    for (int i = 0; i < 4; i++) { acc[i][0] = pk2(0.f, 0.f); acc[i][1] = pk2(0.f, 0.f); }

#pragma unroll
    for (int kk = 0; kk < 16; kk++) {
        const float4 w0 = Ws[kk * 4 + 0][ct];
        const float4 w1 = Ws[kk * 4 + 1][ct];
        const float4 w2 = Ws[kk * 4 + 2][ct];
        const float4 w3 = Ws[kk * 4 + 3][ct];
        const unsigned long long wp00 = pk2(w0.x, w0.y), wp01 = pk2(w0.z, w0.w);
        const unsigned long long wp10 = pk2(w1.x, w1.y), wp11 = pk2(w1.z, w1.w);
        const unsigned long long wp20 = pk2(w2.x, w2.y), wp21 = pk2(w2.z, w2.w);
        const unsigned long long wp30 = pk2(w3.x, w3.y), wp31 = pk2(w3.z, w3.w);
#pragma unroll
        for (int i = 0; i < 4; i++) {
            const float4 x = Xs[rt + 16 * i][kk];
            unsigned long long xx;
            xx = pk2(x.x, x.x); fma2(acc[i][0], xx, wp00); fma2(acc[i][1], xx, wp01);
            xx = pk2(x.y, x.y); fma2(acc[i][0], xx, wp10); fma2(acc[i][1], xx, wp11);
            xx = pk2(x.z, x.z); fma2(acc[i][0], xx, wp20); fma2(acc[i][1], xx, wp21);
            xx = pk2(x.w, x.w); fma2(acc[i][0], xx, wp30); fma2(acc[i][1], xx, wp31);
        }
    }

#pragma unroll
    for (int i = 0; i < 4; i++) {
        const int row = base + rt + 16 * i;
        const float2 a = up2(acc[i][0]);
        const float2 b = up2(acc[i][1]);
        const __half2 ha = __floats2half2_rn(a.x, a.y);
        const __half2 hb = __floats2half2_rn(b.x, b.y);
        uint2 st;
        st.x = *(const unsigned*)&ha;
        st.y = *(const unsigned*)&hb;
        *(uint2*)(g_support_h + (size_t)row * FEAT + ct * 4) = st;
    }
}

// ---------------------------------------------------------------------------
// CSR build
// ---------------------------------------------------------------------------
__global__ __launch_bounds__(256) void zero_cnt() {
    ((int4*)g_cnt)[blockIdx.x * 256 + threadIdx.x] = make_int4(0, 0, 0, 0);
}

__global__ __launch_bounds__(256) void hist(const int4* __restrict__ erow4) {
    const unsigned i = blockIdx.x * 256u + threadIdx.x;
    const int4 r = erow4[i];
    atomicAdd(&g_cnt[r.x], 1);
    atomicAdd(&g_cnt[r.y], 1);
    atomicAdd(&g_cnt[r.z], 1);
    atomicAdd(&g_cnt[r.w], 1);
}

__device__ __forceinline__ int block_incl_scan(int v, int* wsum) {
    const int lane = threadIdx.x & 31, wid = threadIdx.x >> 5;
    int x = v;
#pragma unroll
    for (int d = 1; d < 32; d <<= 1) {
        int y = __shfl_up_sync(0xFFFFFFFFu, x, d);
        if (lane >= d) x += y;
    }
    if (lane == 31) wsum[wid] = x;
    __syncthreads();
    if (wid == 0) {
        int w = (lane < 8) ? wsum[lane] : 0;
#pragma unroll
        for (int d = 1; d < 8; d <<= 1) {
            int y = __shfl_up_sync(0xFFFFFFFFu, w, d);
            if (lane >= d) w += y;
        }
        if (lane < 8) wsum[lane] = w;
    }
    __syncthreads();
    return x + (wid > 0 ? wsum[wid - 1] : 0);
}

// 4 elements per thread: 64 blocks x 256 threads x 4
__global__ __launch_bounds__(256) void scanA() {
    __shared__ int wsum[8];
    const int i = blockIdx.x * 256 + threadIdx.x;
    const int4 c = ((const int4*)g_cnt)[i];
    const int s = c.x + c.y + c.z + c.w;
    const int incl = block_incl_scan(s, wsum);
    const int ex = incl - s;
    ((int4*)g_rs)[i] = make_int4(ex, ex + c.x, ex + c.x + c.y, ex + c.x + c.y + c.z);
    if (threadIdx.x == 255) g_bsum[blockIdx.x] = incl;
}

__global__ __launch_bounds__(256) void scanB() {
    __shared__ int wsum[8];
    const int t = threadIdx.x;
    const int v = (t < 64) ? g_bsum[t] : 0;
    const int incl = block_incl_scan(v, wsum);
    if (t < 64) g_boff[t] = incl - v;
}

__global__ __launch_bounds__(256) void scanC() {
    const int i = blockIdx.x * 256 + threadIdx.x;
    const int off = g_boff[blockIdx.x];
    int4 rs = ((int4*)g_rs)[i];
    rs.x += off; rs.y += off; rs.z += off; rs.w += off;
    ((int4*)g_rs)[i]  = rs;
    ((int4*)g_cur)[i] = rs;
    if (i == 0) g_rs[N_NODES] = N_EDGES;
}

__global__ __launch_bounds__(256) void reorder(const int4*   __restrict__ erow4,
                                               const int4*   __restrict__ ecol4,
                                               const float4* __restrict__ eval4) {
    const unsigned i = blockIdx.x * 256u + threadIdx.x;
    const int4   r = erow4[i];
    const int4   c = ecol4[i];
    const float4 v = eval4[i];
    int p;
    p = atomicAdd(&g_cur[r.x], 1); g_epair[p] = make_int2(c.x, __float_as_int(v.x));
    p = atomicAdd(&g_cur[r.y], 1); g_epair[p] = make_int2(c.y, __float_as_int(v.y));
    p = atomicAdd(&g_cur[r.z], 1); g_epair[p] = make_int2(c.z, __float_as_int(v.z));
    p = atomicAdd(&g_cur[r.w], 1); g_epair[p] = make_int2(c.w, __float_as_int(v.w));
}

// ---------------------------------------------------------------------------
// SpMM + bias + ReLU (atomic-free), fp16 gather, fp32 accumulate
// 8 threads per row (8 halves each); 32 rows per block.
// ---------------------------------------------------------------------------
__global__ __launch_bounds__(256) void spmm_fused(float* __restrict__ out,
                                                  const float* __restrict__ bias) {
    const int r  = blockIdx.x * 32 + (threadIdx.x >> 3);
    const int qi = threadIdx.x & 7;        // which group of 8 halves

    const int s = g_rs[r];
    const int e = g_rs[r + 1];

    float acc[8];
#pragma unroll
    for (int j = 0; j < 8; j++) acc[j] = 0.f;

    for (int i = s; i < e; i++) {
        const int2 p = g_epair[i];
        const float v = __int_as_float(p.y);
        const uint4 h = *(const uint4*)(g_support_h + ((size_t)p.x << 6) + (qi << 3));
        const float2 f0 = __half22float2(*(const __half2*)&h.x);
        const float2 f1 = __half22float2(*(const __half2*)&h.y);
        const float2 f2 = __half22float2(*(const __half2*)&h.z);
        const float2 f3 = __half22float2(*(const __half2*)&h.w);
        acc[0] += v * f0.x; acc[1] += v * f0.y;
        acc[2] += v * f1.x; acc[3] += v * f1.y;
        acc[4] += v * f2.x; acc[5] += v * f2.y;
        acc[6] += v * f3.x; acc[7] += v * f3.y;
    }

    const float4 b0 = *(const float4*)(bias + qi * 8);
    const float4 b1 = *(const float4*)(bias + qi * 8 + 4);
    float4 o0, o1;
    o0.x = fmaxf(acc[0] + b0.x, 0.f); o0.y = fmaxf(acc[1] + b0.y, 0.f);
    o0.z = fmaxf(acc[2] + b0.z, 0.f); o0.w = fmaxf(acc[3] + b0.w, 0.f);
    o1.x = fmaxf(acc[4] + b1.x, 0.f); o1.y = fmaxf(acc[5] + b1.y, 0.f);
    o1.z = fmaxf(acc[6] + b1.z, 0.f); o1.w = fmaxf(acc[7] + b1.w, 0.f);
    float* po = out + (size_t)r * FEAT + qi * 8;
    *(float4*)po       = o0;
    *(float4*)(po + 4) = o1;
}

// ---------------------------------------------------------------------------
extern "C" void kernel_launch(void* const* d_in, const int* in_sizes, int n_in,
                              void* d_out, int out_size) {
    const float* X    = (const float*)d_in[0];
    const int*   erow = (const int*)  d_in[1];
    const int*   ecol = (const int*)  d_in[2];
    const float* eval = (const float*)d_in[3];
    const float* W    = (const float*)d_in[4];
    const float* bias = (const float*)d_in[5];
    float* out = (float*)d_out;

    // CSR build prologue
    zero_cnt<<<N_NODES / 1024, 256>>>();
    hist<<<N_EDGES / 1024, 256>>>((const int4*)erow);

    // GEMM (independent of CSR chain)
    gemm64<<<N_NODES / 64, 256>>>(X, W);

    scanA<<<64, 256>>>();
    scanB<<<1, 256>>>();
    scanC<<<64, 256>>>();
    reorder<<<N_EDGES / 1024, 256>>>((const int4*)erow, (const int4*)ecol,
                                     (const float4*)eval);

    // Fused SpMM + bias + ReLU
    spmm_fused<<<N_NODES / 32, 256>>>(out, bias);
}